// round 13
// baseline (speedup 1.0000x reference)
#include <cuda_runtime.h>
#include <cuda_bf16.h>
#include <cuda_fp16.h>
#include <math.h>
#include <stdint.h>

// ---------------------------------------------------------------------------
// Problem constants
// ---------------------------------------------------------------------------
#define BW      2048
#define NTOK    98
#define DIM     256
#define NH      8
#define HD      32
#define TBL     507
#define HID     512
#define M_ROWS  (BW * NTOK)    // 200704
#define MTILES  (M_ROWS / 128) // 1568

typedef unsigned long long ull;

// ---------------------------------------------------------------------------
// packed fp32x2 helpers
// ---------------------------------------------------------------------------
__device__ __forceinline__ ull ffma2(ull a, ull b, ull c) {
    ull d;
    asm("fma.rn.f32x2 %0, %1, %2, %3;" : "=l"(d) : "l"(a), "l"(b), "l"(c));
    return d;
}
__device__ __forceinline__ ull pack2(float x, float y) {
    ull r;
    asm("mov.b64 %0, {%1, %2};" : "=l"(r) : "f"(x), "f"(y));
    return r;
}
__device__ __forceinline__ float lo32(ull v) { return __uint_as_float((unsigned)v); }
__device__ __forceinline__ float hi32(ull v) { return __uint_as_float((unsigned)(v >> 32)); }

// ---------------------------------------------------------------------------
// mma / ldmatrix / cp.async helpers
// ---------------------------------------------------------------------------
__device__ __forceinline__ uint32_t smem_u32(const void* p) {
    uint32_t a;
    asm("{ .reg .u64 t; cvta.to.shared.u64 t, %1; cvt.u32.u64 %0, t; }"
        : "=r"(a) : "l"(p));
    return a;
}

__device__ __forceinline__ void ldsm_x4(uint32_t* r, uint32_t addr) {
    asm volatile("ldmatrix.sync.aligned.m8n8.x4.shared.b16 {%0,%1,%2,%3}, [%4];"
                 : "=r"(r[0]), "=r"(r[1]), "=r"(r[2]), "=r"(r[3]) : "r"(addr));
}

__device__ __forceinline__ void mma16816h(float* c, const uint32_t* a,
                                          uint32_t b0, uint32_t b1) {
    asm volatile("mma.sync.aligned.m16n8k16.row.col.f32.f16.f16.f32 "
                 "{%0,%1,%2,%3}, {%4,%5,%6,%7}, {%8,%9}, {%0,%1,%2,%3};"
                 : "+f"(c[0]), "+f"(c[1]), "+f"(c[2]), "+f"(c[3])
                 : "r"(a[0]), "r"(a[1]), "r"(a[2]), "r"(a[3]),
                   "r"(b0), "r"(b1));
}

#define CP16(dst, src) \
    asm volatile("cp.async.cg.shared.global [%0], [%1], 16;" \
                 :: "r"(dst), "l"(src) : "memory")
#define CP_COMMIT() asm volatile("cp.async.commit_group;" ::: "memory")
#define CP_WAIT2()  asm volatile("cp.async.wait_group 2;" ::: "memory")
#define CP_WAIT1()  asm volatile("cp.async.wait_group 1;" ::: "memory")
#define CP_WAIT0()  asm volatile("cp.async.wait_group 0;" ::: "memory")

// ---------------------------------------------------------------------------
// Device scratch
// ---------------------------------------------------------------------------
__device__ float g_qkv[3ull * BW * NH * NTOK * HD];
__device__ __half g_xh[(size_t)M_ROWS * DIM];
__device__ __half g_xl[(size_t)M_ROWS * DIM];
__device__ __half g_oh[(size_t)M_ROWS * DIM];
__device__ __half g_ol[(size_t)M_ROWS * DIM];
__device__ __half g_wq[768 * DIM];
__device__ __half g_wp[DIM * DIM];
__device__ float g_rpbT[NH * NTOK * NTOK];   // transposed: [h][j(key)][i(query)]

// ---------------------------------------------------------------------------
// fp16 hi/lo split
// ---------------------------------------------------------------------------
__device__ __forceinline__ void split_f16(float x, unsigned short& h, unsigned short& l) {
    __half hb = __float2half_rn(x);
    float hf = __half2float(hb);
    __half lb = __float2half_rn(x - hf);
    h = __half_as_ushort(hb);
    l = __half_as_ushort(lb);
}

// ---------------------------------------------------------------------------
// Fused converter: blocks [0, NBX) split x hi/lo; [NBX, NBX+NBQ) cvt qkv_w;
// rest cvt proj_w.
// ---------------------------------------------------------------------------
#define N4X  ((M_ROWS * DIM) / 4)       // 12,845,056
#define N4Q  ((768 * DIM) / 4)          // 49,152
#define N4P  ((DIM * DIM) / 4)          // 16,384
#define NBX  ((N4X + 255) / 256)
#define NBQ  ((N4Q + 255) / 256)
#define NBP  ((N4P + 255) / 256)

__global__ __launch_bounds__(256)
void cvt_all_kernel(const float4* __restrict__ x,
                    const float4* __restrict__ wq_f,
                    const float4* __restrict__ wp_f)
{
    int bid = blockIdx.x;
    if (bid < NBX) {
        int i = bid * 256 + threadIdx.x;
        if (i >= N4X) return;
        float4 v = x[i];
        unsigned short h0,h1,h2,h3,l0,l1,l2,l3;
        split_f16(v.x, h0, l0);
        split_f16(v.y, h1, l1);
        split_f16(v.z, h2, l2);
        split_f16(v.w, h3, l3);
        uint2 H, L;
        H.x = (uint32_t)h0 | ((uint32_t)h1 << 16);
        H.y = (uint32_t)h2 | ((uint32_t)h3 << 16);
        L.x = (uint32_t)l0 | ((uint32_t)l1 << 16);
        L.y = (uint32_t)l2 | ((uint32_t)l3 << 16);
        ((uint2*)g_xh)[i] = H;
        ((uint2*)g_xl)[i] = L;
    } else if (bid < NBX + NBQ) {
        int i = (bid - NBX) * 256 + threadIdx.x;
        if (i >= N4Q) return;
        float4 v = wq_f[i];
        __half2 p0 = __floats2half2_rn(v.x, v.y);
        __half2 p1 = __floats2half2_rn(v.z, v.w);
        uint2 o;
        o.x = *(uint32_t*)&p0;
        o.y = *(uint32_t*)&p1;
        ((uint2*)g_wq)[i] = o;
    } else {
        int i = (bid - NBX - NBQ) * 256 + threadIdx.x;
        if (i >= N4P) return;
        float4 v = wp_f[i];
        __half2 p0 = __floats2half2_rn(v.x, v.y);
        __half2 p1 = __floats2half2_rn(v.z, v.w);
        uint2 o;
        o.x = *(uint32_t*)&p0;
        o.y = *(uint32_t*)&p1;
        ((uint2*)g_wp)[i] = o;
    }
}

// ---------------------------------------------------------------------------
// Fused CPB MLP + rpb gather: each block computes the FULL bt table (507x8)
// in smem, then writes its slice of rpbT.
// ---------------------------------------------------------------------------
__device__ __forceinline__ float rel_coord(float x, float w) {
    float t = x / (w - 1.0f + 1e-6f) * 8.0f;
    float l = log2f(fabsf(t) + 1.0f) * (1.0f / 3.0f);
    return (t > 0.0f) ? l : ((t < 0.0f) ? -l : 0.0f);
}

#define RPB_TOTAL (NH * NTOK * NTOK)     // 76832
#define RPB_PER_BLK 1024
#define RPB_BLKS ((RPB_TOTAL + RPB_PER_BLK - 1) / RPB_PER_BLK)   // 76

__global__ __launch_bounds__(256)
void rpb_fused_kernel(const float* __restrict__ w1,
                      const float* __restrict__ b1,
                      const float* __restrict__ w2)
{
    __shared__ float s_w1[HID * 3];
    __shared__ float s_b1[HID];
    __shared__ float s_w2[NH * HID];
    __shared__ float s_bt[TBL * NH];

    int tid = threadIdx.x;
    for (int i = tid; i < HID * 3; i += 256) s_w1[i] = w1[i];
    for (int i = tid; i < HID; i += 256)     s_b1[i] = b1[i];
    for (int i = tid; i < NH * HID; i += 256) s_w2[i] = w2[i];
    __syncthreads();

    // compute full bt table (each thread: ~2 entries)
    for (int t = tid; t < TBL; t += 256) {
        int a = t / 169;
        int b = (t / 13) % 13;
        int c = t % 13;
        float c0 = rel_coord((float)(a - 1), 2.0f);
        float c1 = rel_coord((float)(b - 6), 7.0f);
        float c2 = rel_coord((float)(c - 6), 7.0f);
        float acc[NH];
#pragma unroll
        for (int h = 0; h < NH; h++) acc[h] = 0.0f;
        for (int j = 0; j < HID; j++) {
            float hv = s_w1[j*3+0]*c0 + s_w1[j*3+1]*c1 + s_w1[j*3+2]*c2 + s_b1[j];
            hv = fmaxf(hv, 0.0f);
#pragma unroll
            for (int h = 0; h < NH; h++) acc[h] += hv * s_w2[h*HID + j];
        }
#pragma unroll
        for (int h = 0; h < NH; h++) s_bt[t*NH + h] = acc[h];
    }
    __syncthreads();

    // write rpbT slice
    int base = blockIdx.x * RPB_PER_BLK;
#pragma unroll
    for (int k = 0; k < RPB_PER_BLK / 256; k++) {
        int idx = base + k * 256 + tid;
        if (idx >= RPB_TOTAL) return;
        int h = idx / (NTOK * NTOK);
        int r = idx % (NTOK * NTOK);
        int j = r / NTOK, i = r % NTOK;
        int di = i / 49, hi = (i / 7) % 7, wi = i % 7;
        int dj = j / 49, hj = (j / 7) % 7, wj = j % 7;
        int t = (di - dj + 1) * 169 + (hi - hj + 6) * 13 + (wi - wj + 6);
        float v = s_bt[t*NH + h];
        g_rpbT[idx] = 16.0f / (1.0f + __expf(-v));
    }
}

// ---------------------------------------------------------------------------
// fp16 2-pass GEMM — identical to R12.
// ---------------------------------------------------------------------------
#define MATB  8192
#define STGB  (3 * MATB)
#define NSTG  3
#define GEMM_SMEM (NSTG * STGB)

__device__ __forceinline__ uint32_t sw64(int r, int c) {
    return (uint32_t)r * 64u + (uint32_t)((c ^ (r & 3)) << 4);
}

template<bool IS_QKV>
__global__ __launch_bounds__(256, 2)
void gemm_mma(const __half* __restrict__ Ah,
              const __half* __restrict__ Al,
              const __half* __restrict__ Bf,
              float* __restrict__ outp,
              const float* __restrict__ qb,
              const float* __restrict__ vb,
              const float* __restrict__ pb)
{
    extern __shared__ __align__(16) unsigned char smc[];
    const uint32_t sb = smem_u32(smc);

    int tid  = threadIdx.x;
    int lane = tid & 31;
    int wid  = tid >> 5;
    int wm   = wid & 3;
    int wn   = wid >> 2;
    int n0   = blockIdx.x * 128;
    int m0   = blockIdx.y * 128;

    const char* srcs[3] = {
        (const char*)Ah + (size_t)m0 * 512,
        (const char*)Al + (size_t)m0 * 512,
        (const char*)Bf + (size_t)n0 * 512
    };

    auto issue = [&](int ck, int buf) {
        uint32_t st = sb + (uint32_t)buf * STGB;
#pragma unroll
        for (int t = 0; t < 6; t++) {
            int m = t >> 1;
            int s = tid + (t & 1) * 256;
            int r = s >> 2, c = s & 3;
            uint32_t dst = st + (uint32_t)m * MATB + sw64(r, c);
            const char* src = srcs[m] + (size_t)r * 512 + ck * 64 + c * 16;
            CP16(dst, src);
        }
    };

    issue(0, 0); CP_COMMIT();
    issue(1, 1); CP_COMMIT();
    issue(2, 2); CP_COMMIT();

    int aRow = wm * 32 + (lane & 15);
    int aC   = lane >> 4;
    int bRow = wn * 64 + (lane & 7) + ((lane >> 4) & 1) * 8;
    int bC   = (lane >> 3) & 1;

    float acc[2][8][4];
#pragma unroll
    for (int i = 0; i < 2; i++)
#pragma unroll
        for (int j = 0; j < 8; j++)
#pragma unroll
            for (int k = 0; k < 4; k++) acc[i][j][k] = 0.0f;

    for (int c = 0; c < 8; c++) {
        if (c <= 5)      CP_WAIT2();
        else if (c == 6) CP_WAIT1();
        else             CP_WAIT0();
        __syncthreads();

        uint32_t st = sb + (uint32_t)(c % 3) * STGB;
        uint32_t stAH = st, stAL = st + MATB, stBF = st + 2*MATB;

#pragma unroll
        for (int kk = 0; kk < 2; kk++) {
            uint32_t ah[2][4], al[2][4];
#pragma unroll
            for (int mt = 0; mt < 2; mt++) {
                int r = aRow + mt * 16;
                uint32_t off = sw64(r, aC + 2 * kk);
                ldsm_x4(ah[mt], stAH + off);
                ldsm_x4(al[mt], stAL + off);
            }
#pragma unroll
            for (int pr = 0; pr < 4; pr++) {
                int r = bRow + pr * 16;
                uint32_t off = sw64(r, bC + 2 * kk);
                uint32_t bf4[4];
                ldsm_x4(bf4, stBF + off);
#pragma unroll
                for (int mt = 0; mt < 2; mt++)
#pragma unroll
                    for (int hf = 0; hf < 2; hf++) {
                        int w2 = hf * 2;
                        float* a4 = acc[mt][pr * 2 + hf];
                        mma16816h(a4, ah[mt], bf4[w2], bf4[w2+1]);
                        mma16816h(a4, al[mt], bf4[w2], bf4[w2+1]);
                    }
            }
        }
        __syncthreads();
        if (c + 3 < 8) { issue(c + 3, c % 3); CP_COMMIT(); }
    }

    const size_t tstride = (size_t)BW * NH * NTOK * HD;
#pragma unroll
    for (int mt = 0; mt < 2; mt++) {
        int rA = m0 + wm*32 + mt*16 + (lane >> 2);
#pragma unroll
        for (int nt8 = 0; nt8 < 8; nt8++) {
            int n = n0 + wn*64 + nt8*8 + (lane & 3) * 2;
            if (IS_QKV) {
                int which = n >> 8;
                int h = (n >> 5) & 7;
                int d = n & 31;
                float2 bv = make_float2(0.f, 0.f);
                if (which == 0)      bv = *(const float2*)(qb + (n & 255));
                else if (which == 2) bv = *(const float2*)(vb + (n & 255));
                {
                    int bwin = rA / NTOK, tok = rA - bwin * NTOK;
                    float* dst = g_qkv + (size_t)which * tstride
                               + (((size_t)bwin * NH + h) * NTOK + tok) * HD + d;
                    *(float2*)dst = make_float2(acc[mt][nt8][0] + bv.x,
                                                acc[mt][nt8][1] + bv.y);
                }
                {
                    int r2 = rA + 8;
                    int bwin = r2 / NTOK, tok = r2 - bwin * NTOK;
                    float* dst = g_qkv + (size_t)which * tstride
                               + (((size_t)bwin * NH + h) * NTOK + tok) * HD + d;
                    *(float2*)dst = make_float2(acc[mt][nt8][2] + bv.x,
                                                acc[mt][nt8][3] + bv.y);
                }
            } else {
                float2 bv = *(const float2*)(pb + n);
                *(float2*)(outp + (size_t)rA * DIM + n) =
                    make_float2(acc[mt][nt8][0] + bv.x, acc[mt][nt8][1] + bv.y);
                *(float2*)(outp + (size_t)(rA + 8) * DIM + n) =
                    make_float2(acc[mt][nt8][2] + bv.x, acc[mt][nt8][3] + bv.y);
            }
        }
    }
}

// ---------------------------------------------------------------------------
// fused cosine attention — identical to R12.
// ---------------------------------------------------------------------------
#define QPAD 36
#define ATTN_SMEM (2 * NTOK * QPAD * 4)

__global__ __launch_bounds__(128)
void attn_kernel(const float* __restrict__ logit_scale)
{
    extern __shared__ float sm[];
    float* ks = sm;
    float* vs = sm + NTOK * QPAD;

    int bh = blockIdx.x;
    int b = bh >> 3;
    int h = bh & 7;
    int tid = threadIdx.x;

    const size_t tensor_stride = (size_t)BW * NH * NTOK * HD;
    size_t base = ((size_t)b * NH + h) * (NTOK * HD);
    const float* Q  = g_qkv + base;
    const float* Kp = g_qkv + tensor_stride + base;
    const float* Vp = g_qkv + 2 * tensor_stride + base;
    const float* rpbT_h = g_rpbT + (size_t)h * (NTOK * NTOK);

    for (int idx = tid; idx < NTOK * HD; idx += 128) {
        int r = idx >> 5, d = idx & 31;
        ks[r*QPAD + d] = Kp[idx];
        vs[r*QPAD + d] = Vp[idx];
    }
    __syncthreads();

    float scale = __expf(fminf(logit_scale[h], 4.6051702f));
    float smax = scale + 16.0f;

    int i = tid;
    ull q2[16];
    if (i < NTOK) {
        const float4* Qr = (const float4*)(Q + (size_t)i * HD);
        float qr[HD];
        float nq = 0.f;
#pragma unroll
        for (int c = 0; c < 8; c++) {
            float4 t = Qr[c];
            qr[c*4+0] = t.x; qr[c*4+1] = t.y; qr[c*4+2] = t.z; qr[c*4+3] = t.w;
            nq += t.x*t.x + t.y*t.y + t.z*t.z + t.w*t.w;
        }
        float rq = scale / fmaxf(sqrtf(nq), 1e-12f);
#pragma unroll
        for (int c = 0; c < 16; c++)
            q2[c] = pack2(qr[c*2] * rq, qr[c*2+1] * rq);

        float nk = 0.f;
#pragma unroll
        for (int d = 0; d < HD; d++) {
            float k = ks[i*QPAD + d];
            nk += k * k;
        }
        float rk = 1.0f / fmaxf(sqrtf(nk), 1e-12f);
#pragma unroll
        for (int c = 0; c < 8; c++) {
            float4 k4 = *(float4*)&ks[i*QPAD + c*4];
            k4.x *= rk; k4.y *= rk; k4.z *= rk; k4.w *= rk;
            *(float4*)&ks[i*QPAD + c*4] = k4;
        }
    }
    __syncthreads();

    if (i < NTOK) {
        float sum = 0.f;
        ull accv2[16];
#pragma unroll
        for (int c = 0; c < 16; c++) accv2[c] = 0ull;

        for (int j = 0; j < NTOK; j++) {
            const ulonglong2* kr = (const ulonglong2*)(ks + j*QPAD);
            ull s2a = 0ull, s2b = 0ull;
#pragma unroll
            for (int c = 0; c < 8; c += 2) {
                ulonglong2 ka = kr[c];
                ulonglong2 kb = kr[c+1];
                s2a = ffma2(q2[c*2+0], ka.x, s2a);
                s2b = ffma2(q2[c*2+1], ka.y, s2b);
                s2a = ffma2(q2[c*2+2], kb.x, s2a);
                s2b = ffma2(q2[c*2+3], kb.y, s2b);
            }
            float s = lo32(s2a) + hi32(s2a) + lo32(s2b) + hi32(s2b)
                    + rpbT_h[j * NTOK + i];
            float e = __expf(s - smax);
            sum += e;
            ull p2 = pack2(e, e);
            const ulonglong2* vr = (const ulonglong2*)(vs + j*QPAD);
#pragma unroll
            for (int c = 0; c < 8; c++) {
                ulonglong2 v2 = vr[c];
                accv2[c*2+0] = ffma2(p2, v2.x, accv2[c*2+0]);
                accv2[c*2+1] = ffma2(p2, v2.y, accv2[c*2+1]);
            }
        }
        float inv = 1.0f / sum;

        size_t row = ((size_t)b * NTOK + i) * DIM + (size_t)h * HD;
        uint32_t* ohp = (uint32_t*)(g_oh + row);
        uint32_t* olp = (uint32_t*)(g_ol + row);
#pragma unroll
        for (int c = 0; c < 16; c++) {
            float v0 = lo32(accv2[c]) * inv;
            float v1 = hi32(accv2[c]) * inv;
            unsigned short h0, h1, l0, l1;
            split_f16(v0, h0, l0);
            split_f16(v1, h1, l1);
            ohp[c] = (uint32_t)h0 | ((uint32_t)h1 << 16);
            olp[c] = (uint32_t)l0 | ((uint32_t)l1 << 16);
        }
    }
}

// ---------------------------------------------------------------------------
// kernel_launch — 5 launches; index 3 = attn_kernel (profiled)
// ---------------------------------------------------------------------------
extern "C" void kernel_launch(void* const* d_in, const int* in_sizes, int n_in,
                              void* d_out, int out_size)
{
    const float* x           = (const float*)d_in[0];
    const float* qkv_w       = (const float*)d_in[1];
    const float* q_bias      = (const float*)d_in[2];
    const float* v_bias      = (const float*)d_in[3];
    const float* logit_scale = (const float*)d_in[4];
    const float* cpb_w1      = (const float*)d_in[5];
    const float* cpb_b1      = (const float*)d_in[6];
    const float* cpb_w2      = (const float*)d_in[7];
    const float* proj_w      = (const float*)d_in[8];
    const float* proj_b      = (const float*)d_in[9];
    float* out = (float*)d_out;

    __half *xh, *xl, *oh, *ol, *wq, *wp;
    cudaGetSymbolAddress((void**)&xh, g_xh);
    cudaGetSymbolAddress((void**)&xl, g_xl);
    cudaGetSymbolAddress((void**)&oh, g_oh);
    cudaGetSymbolAddress((void**)&ol, g_ol);
    cudaGetSymbolAddress((void**)&wq, g_wq);
    cudaGetSymbolAddress((void**)&wp, g_wp);

    static bool attr_set = false;
    if (!attr_set) {
        cudaFuncSetAttribute(attn_kernel,
                             cudaFuncAttributeMaxDynamicSharedMemorySize, ATTN_SMEM);
        cudaFuncSetAttribute(gemm_mma<true>,
                             cudaFuncAttributeMaxDynamicSharedMemorySize, GEMM_SMEM);
        cudaFuncSetAttribute(gemm_mma<false>,
                             cudaFuncAttributeMaxDynamicSharedMemorySize, GEMM_SMEM);
        attr_set = true;
    }

    // 0: fused converters (x hi/lo + both weights)
    cvt_all_kernel<<<NBX + NBQ + NBP, 256>>>((const float4*)x,
                                             (const float4*)qkv_w,
                                             (const float4*)proj_w);

    // 1: QKV GEMM
    {
        dim3 grid(6, MTILES);
        gemm_mma<true><<<grid, 256, GEMM_SMEM>>>(xh, xl, wq,
                                                 nullptr, q_bias, v_bias, nullptr);
    }

    // 2: fused cpb + rpb
    rpb_fused_kernel<<<RPB_BLKS, 256>>>(cpb_w1, cpb_b1, cpb_w2);

    // 3: fused attention  <-- profiled launch index
    attn_kernel<<<BW * NH, 128, ATTN_SMEM>>>(logit_scale);

    // 4: proj GEMM
    {
        dim3 grid(2, MTILES);
        gemm_mma<false><<<grid, 256, GEMM_SMEM>>>(oh, ol, wp,
                                                  out, nullptr, nullptr, proj_b);
    }
}

// round 16
// speedup vs baseline: 1.1361x; 1.1361x over previous
#include <cuda_runtime.h>
#include <cuda_fp16.h>
#include <math.h>
#include <stdint.h>

// ---------------------------------------------------------------------------
// Problem constants
// ---------------------------------------------------------------------------
#define BW      2048
#define NTOK    98
#define DIM     256
#define NH      8
#define HD      32
#define TBL     507
#define HID     512
#define M_ROWS  (BW * NTOK)    // 200704
#define MTILES  (M_ROWS / 128) // 1568

typedef unsigned long long ull;

// ---------------------------------------------------------------------------
// mma / ldmatrix / cp.async helpers
// ---------------------------------------------------------------------------
__device__ __forceinline__ uint32_t smem_u32(const void* p) {
    uint32_t a;
    asm("{ .reg .u64 t; cvta.to.shared.u64 t, %1; cvt.u32.u64 %0, t; }"
        : "=r"(a) : "l"(p));
    return a;
}

__device__ __forceinline__ void ldsm_x4(uint32_t* r, uint32_t addr) {
    asm volatile("ldmatrix.sync.aligned.m8n8.x4.shared.b16 {%0,%1,%2,%3}, [%4];"
                 : "=r"(r[0]), "=r"(r[1]), "=r"(r[2]), "=r"(r[3]) : "r"(addr));
}

__device__ __forceinline__ void mma16816h(float* c, const uint32_t* a,
                                          uint32_t b0, uint32_t b1) {
    asm volatile("mma.sync.aligned.m16n8k16.row.col.f32.f16.f16.f32 "
                 "{%0,%1,%2,%3}, {%4,%5,%6,%7}, {%8,%9}, {%0,%1,%2,%3};"
                 : "+f"(c[0]), "+f"(c[1]), "+f"(c[2]), "+f"(c[3])
                 : "r"(a[0]), "r"(a[1]), "r"(a[2]), "r"(a[3]),
                   "r"(b0), "r"(b1));
}

#define CP16(dst, src) \
    asm volatile("cp.async.cg.shared.global [%0], [%1], 16;" \
                 :: "r"(dst), "l"(src) : "memory")
#define CP_COMMIT() asm volatile("cp.async.commit_group;" ::: "memory")
#define CP_WAIT2()  asm volatile("cp.async.wait_group 2;" ::: "memory")
#define CP_WAIT1()  asm volatile("cp.async.wait_group 1;" ::: "memory")
#define CP_WAIT0()  asm volatile("cp.async.wait_group 0;" ::: "memory")

// ---------------------------------------------------------------------------
// Device scratch
// ---------------------------------------------------------------------------
__device__ float g_qkv[3ull * BW * NH * NTOK * HD];
__device__ __half g_xh[(size_t)M_ROWS * DIM];
__device__ __half g_xl[(size_t)M_ROWS * DIM];
__device__ __half g_oh[(size_t)M_ROWS * DIM];
__device__ __half g_ol[(size_t)M_ROWS * DIM];
__device__ __half g_wq[768 * DIM];
__device__ __half g_wp[DIM * DIM];
__device__ float g_rpb[NH * NTOK * NTOK];   // [h][i(query)][j(key)]

// ---------------------------------------------------------------------------
// fp16 hi/lo split helpers
// ---------------------------------------------------------------------------
__device__ __forceinline__ void split_f16(float x, unsigned short& h, unsigned short& l) {
    __half hb = __float2half_rn(x);
    float hf = __half2float(hb);
    __half lb = __float2half_rn(x - hf);
    h = __half_as_ushort(hb);
    l = __half_as_ushort(lb);
}
__device__ __forceinline__ uint32_t h2pack(float a, float b) {
    __half2 p = __floats2half2_rn(a, b);
    return *(uint32_t*)&p;
}

// ---------------------------------------------------------------------------
// Fused converter
// ---------------------------------------------------------------------------
#define N4X  ((M_ROWS * DIM) / 4)
#define N4Q  ((768 * DIM) / 4)
#define N4P  ((DIM * DIM) / 4)
#define NBX  ((N4X + 255) / 256)
#define NBQ  ((N4Q + 255) / 256)
#define NBP  ((N4P + 255) / 256)

__global__ __launch_bounds__(256)
void cvt_all_kernel(const float4* __restrict__ x,
                    const float4* __restrict__ wq_f,
                    const float4* __restrict__ wp_f)
{
    int bid = blockIdx.x;
    if (bid < NBX) {
        int i = bid * 256 + threadIdx.x;
        if (i >= N4X) return;
        float4 v = x[i];
        unsigned short h0,h1,h2,h3,l0,l1,l2,l3;
        split_f16(v.x, h0, l0);
        split_f16(v.y, h1, l1);
        split_f16(v.z, h2, l2);
        split_f16(v.w, h3, l3);
        uint2 H, L;
        H.x = (uint32_t)h0 | ((uint32_t)h1 << 16);
        H.y = (uint32_t)h2 | ((uint32_t)h3 << 16);
        L.x = (uint32_t)l0 | ((uint32_t)l1 << 16);
        L.y = (uint32_t)l2 | ((uint32_t)l3 << 16);
        ((uint2*)g_xh)[i] = H;
        ((uint2*)g_xl)[i] = L;
    } else if (bid < NBX + NBQ) {
        int i = (bid - NBX) * 256 + threadIdx.x;
        if (i >= N4Q) return;
        float4 v = wq_f[i];
        uint2 o;
        o.x = h2pack(v.x, v.y);
        o.y = h2pack(v.z, v.w);
        ((uint2*)g_wq)[i] = o;
    } else {
        int i = (bid - NBX - NBQ) * 256 + threadIdx.x;
        if (i >= N4P) return;
        float4 v = wp_f[i];
        uint2 o;
        o.x = h2pack(v.x, v.y);
        o.y = h2pack(v.z, v.w);
        ((uint2*)g_wp)[i] = o;
    }
}

// ---------------------------------------------------------------------------
// Fused CPB MLP + rpb gather ([h][i][j])
// ---------------------------------------------------------------------------
__device__ __forceinline__ float rel_coord(float x, float w) {
    float t = x / (w - 1.0f + 1e-6f) * 8.0f;
    float l = log2f(fabsf(t) + 1.0f) * (1.0f / 3.0f);
    return (t > 0.0f) ? l : ((t < 0.0f) ? -l : 0.0f);
}

#define RPB_TOTAL (NH * NTOK * NTOK)
#define RPB_PER_BLK 1024
#define RPB_BLKS ((RPB_TOTAL + RPB_PER_BLK - 1) / RPB_PER_BLK)

__global__ __launch_bounds__(256)
void rpb_fused_kernel(const float* __restrict__ w1,
                      const float* __restrict__ b1,
                      const float* __restrict__ w2)
{
    __shared__ float s_w1[HID * 3];
    __shared__ float s_b1[HID];
    __shared__ float s_w2[NH * HID];
    __shared__ float s_bt[TBL * NH];

    int tid = threadIdx.x;
    for (int i = tid; i < HID * 3; i += 256) s_w1[i] = w1[i];
    for (int i = tid; i < HID; i += 256)     s_b1[i] = b1[i];
    for (int i = tid; i < NH * HID; i += 256) s_w2[i] = w2[i];
    __syncthreads();

    for (int t = tid; t < TBL; t += 256) {
        int a = t / 169;
        int b = (t / 13) % 13;
        int c = t % 13;
        float c0 = rel_coord((float)(a - 1), 2.0f);
        float c1 = rel_coord((float)(b - 6), 7.0f);
        float c2 = rel_coord((float)(c - 6), 7.0f);
        float acc[NH];
#pragma unroll
        for (int h = 0; h < NH; h++) acc[h] = 0.0f;
        for (int j = 0; j < HID; j++) {
            float hv = s_w1[j*3+0]*c0 + s_w1[j*3+1]*c1 + s_w1[j*3+2]*c2 + s_b1[j];
            hv = fmaxf(hv, 0.0f);
#pragma unroll
            for (int h = 0; h < NH; h++) acc[h] += hv * s_w2[h*HID + j];
        }
#pragma unroll
        for (int h = 0; h < NH; h++) s_bt[t*NH + h] = acc[h];
    }
    __syncthreads();

    int base = blockIdx.x * RPB_PER_BLK;
#pragma unroll
    for (int k = 0; k < RPB_PER_BLK / 256; k++) {
        int idx = base + k * 256 + tid;
        if (idx >= RPB_TOTAL) return;
        int h = idx / (NTOK * NTOK);
        int r = idx % (NTOK * NTOK);
        int i = r / NTOK, j = r % NTOK;
        int di = i / 49, hi = (i / 7) % 7, wi = i % 7;
        int dj = j / 49, hj = (j / 7) % 7, wj = j % 7;
        int t = (di - dj + 1) * 169 + (hi - hj + 6) * 13 + (wi - wj + 6);
        float v = s_bt[t*NH + h];
        g_rpb[idx] = 16.0f / (1.0f + __expf(-v));
    }
}

// ---------------------------------------------------------------------------
// fp16 2-pass GEMM — identical to R12/R13.
// ---------------------------------------------------------------------------
#define MATB  8192
#define STGB  (3 * MATB)
#define NSTG  3
#define GEMM_SMEM (NSTG * STGB)

__device__ __forceinline__ uint32_t sw64(int r, int c) {
    return (uint32_t)r * 64u + (uint32_t)((c ^ (r & 3)) << 4);
}

template<bool IS_QKV>
__global__ __launch_bounds__(256, 2)
void gemm_mma(const __half* __restrict__ Ah,
              const __half* __restrict__ Al,
              const __half* __restrict__ Bf,
              float* __restrict__ outp,
              const float* __restrict__ qb,
              const float* __restrict__ vb,
              const float* __restrict__ pb)
{
    extern __shared__ __align__(16) unsigned char smc[];
    const uint32_t sb = smem_u32(smc);

    int tid  = threadIdx.x;
    int lane = tid & 31;
    int wid  = tid >> 5;
    int wm   = wid & 3;
    int wn   = wid >> 2;
    int n0   = blockIdx.x * 128;
    int m0   = blockIdx.y * 128;

    const char* srcs[3] = {
        (const char*)Ah + (size_t)m0 * 512,
        (const char*)Al + (size_t)m0 * 512,
        (const char*)Bf + (size_t)n0 * 512
    };

    auto issue = [&](int ck, int buf) {
        uint32_t st = sb + (uint32_t)buf * STGB;
#pragma unroll
        for (int t = 0; t < 6; t++) {
            int m = t >> 1;
            int s = tid + (t & 1) * 256;
            int r = s >> 2, c = s & 3;
            uint32_t dst = st + (uint32_t)m * MATB + sw64(r, c);
            const char* src = srcs[m] + (size_t)r * 512 + ck * 64 + c * 16;
            CP16(dst, src);
        }
    };

    issue(0, 0); CP_COMMIT();
    issue(1, 1); CP_COMMIT();
    issue(2, 2); CP_COMMIT();

    int aRow = wm * 32 + (lane & 15);
    int aC   = lane >> 4;
    int bRow = wn * 64 + (lane & 7) + ((lane >> 4) & 1) * 8;
    int bC   = (lane >> 3) & 1;

    float acc[2][8][4];
#pragma unroll
    for (int i = 0; i < 2; i++)
#pragma unroll
        for (int j = 0; j < 8; j++)
#pragma unroll
            for (int k = 0; k < 4; k++) acc[i][j][k] = 0.0f;

    for (int c = 0; c < 8; c++) {
        if (c <= 5)      CP_WAIT2();
        else if (c == 6) CP_WAIT1();
        else             CP_WAIT0();
        __syncthreads();

        uint32_t st = sb + (uint32_t)(c % 3) * STGB;
        uint32_t stAH = st, stAL = st + MATB, stBF = st + 2*MATB;

#pragma unroll
        for (int kk = 0; kk < 2; kk++) {
            uint32_t ah[2][4], al[2][4];
#pragma unroll
            for (int mt = 0; mt < 2; mt++) {
                int r = aRow + mt * 16;
                uint32_t off = sw64(r, aC + 2 * kk);
                ldsm_x4(ah[mt], stAH + off);
                ldsm_x4(al[mt], stAL + off);
            }
#pragma unroll
            for (int pr = 0; pr < 4; pr++) {
                int r = bRow + pr * 16;
                uint32_t off = sw64(r, bC + 2 * kk);
                uint32_t bf4[4];
                ldsm_x4(bf4, stBF + off);
#pragma unroll
                for (int mt = 0; mt < 2; mt++)
#pragma unroll
                    for (int hf = 0; hf < 2; hf++) {
                        int w2 = hf * 2;
                        float* a4 = acc[mt][pr * 2 + hf];
                        mma16816h(a4, ah[mt], bf4[w2], bf4[w2+1]);
                        mma16816h(a4, al[mt], bf4[w2], bf4[w2+1]);
                    }
            }
        }
        __syncthreads();
        if (c + 3 < 8) { issue(c + 3, c % 3); CP_COMMIT(); }
    }

    const size_t tstride = (size_t)BW * NH * NTOK * HD;
#pragma unroll
    for (int mt = 0; mt < 2; mt++) {
        int rA = m0 + wm*32 + mt*16 + (lane >> 2);
#pragma unroll
        for (int nt8 = 0; nt8 < 8; nt8++) {
            int n = n0 + wn*64 + nt8*8 + (lane & 3) * 2;
            if (IS_QKV) {
                int which = n >> 8;
                int h = (n >> 5) & 7;
                int d = n & 31;
                float2 bv = make_float2(0.f, 0.f);
                if (which == 0)      bv = *(const float2*)(qb + (n & 255));
                else if (which == 2) bv = *(const float2*)(vb + (n & 255));
                {
                    int bwin = rA / NTOK, tok = rA - bwin * NTOK;
                    float* dst = g_qkv + (size_t)which * tstride
                               + (((size_t)bwin * NH + h) * NTOK + tok) * HD + d;
                    *(float2*)dst = make_float2(acc[mt][nt8][0] + bv.x,
                                                acc[mt][nt8][1] + bv.y);
                }
                {
                    int r2 = rA + 8;
                    int bwin = r2 / NTOK, tok = r2 - bwin * NTOK;
                    float* dst = g_qkv + (size_t)which * tstride
                               + (((size_t)bwin * NH + h) * NTOK + tok) * HD + d;
                    *(float2*)dst = make_float2(acc[mt][nt8][2] + bv.x,
                                                acc[mt][nt8][3] + bv.y);
                }
            } else {
                float2 bv = *(const float2*)(pb + n);
                *(float2*)(outp + (size_t)rA * DIM + n) =
                    make_float2(acc[mt][nt8][0] + bv.x, acc[mt][nt8][1] + bv.y);
                *(float2*)(outp + (size_t)(rA + 8) * DIM + n) =
                    make_float2(acc[mt][nt8][2] + bv.x, acc[mt][nt8][3] + bv.y);
            }
        }
    }
}

// ---------------------------------------------------------------------------
// MMA attention — P via shared memory, scaled by 2^14 before fp16 cast.
// smem layout:
//   Vt hi [32 x 136 f16]  @ 0      (8704 B)
//   Vt lo                 @ 8704   (8704 B)
//   Qh [128 x 32, sw64]   @ 17408  (8192)
//   Ql                    @ 25600
//   Kh                    @ 33792
//   Kl                    @ 41984
//   P  [128 x 136 f16]    @ 17408  (34816; overwrites Q/K after QK^T)
// ---------------------------------------------------------------------------
#define AT_VH 0
#define AT_VL 8704
#define AT_QH 17408
#define AT_QL 25600
#define AT_KH 33792
#define AT_KL 41984
#define AT_P  17408
#define ATTN_SMEM 52224
#define P_SCALE 16384.0f

__global__ __launch_bounds__(128)
void attn_kernel(const float* __restrict__ logit_scale)
{
    extern __shared__ __align__(16) unsigned char smc[];
    const uint32_t sb = smem_u32(smc);
    int bh = blockIdx.x;
    int b = bh >> 3, h = bh & 7;
    int tid = threadIdx.x;
    int lane = tid & 31, wid = tid >> 5;

    // zero all smem (padding rows/cols must be 0)
    for (int i = tid; i < ATTN_SMEM / 16; i += 128)
        ((uint4*)smc)[i] = make_uint4(0u, 0u, 0u, 0u);
    __syncthreads();

    float scale = __expf(fminf(logit_scale[h], 4.6051702f));
    float smax = scale + 16.0f;

    const size_t tstride = (size_t)BW * NH * NTOK * HD;
    size_t base = ((size_t)b * NH + h) * (NTOK * HD);
    const float* Qg = g_qkv + base;
    const float* Kg = g_qkv + tstride + base;
    const float* Vg = g_qkv + 2 * tstride + base;

    int r = tid;
    if (r < NTOK) {
        float qr[32], kr[32];
        float nq = 0.f, nk = 0.f;
        const float4* Qr = (const float4*)(Qg + (size_t)r * HD);
        const float4* Kr = (const float4*)(Kg + (size_t)r * HD);
#pragma unroll
        for (int c = 0; c < 8; c++) {
            float4 t = Qr[c];
            qr[c*4+0]=t.x; qr[c*4+1]=t.y; qr[c*4+2]=t.z; qr[c*4+3]=t.w;
            nq += t.x*t.x + t.y*t.y + t.z*t.z + t.w*t.w;
            float4 u = Kr[c];
            kr[c*4+0]=u.x; kr[c*4+1]=u.y; kr[c*4+2]=u.z; kr[c*4+3]=u.w;
            nk += u.x*u.x + u.y*u.y + u.z*u.z + u.w*u.w;
        }
        float rq = scale / fmaxf(sqrtf(nq), 1e-12f);
        float rk = 1.0f / fmaxf(sqrtf(nk), 1e-12f);

#pragma unroll
        for (int c = 0; c < 4; c++) {
            uint32_t qh4[4], ql4[4], kh4[4], kl4[4];
#pragma unroll
            for (int e = 0; e < 4; e++) {
                float x0 = qr[c*8 + e*2]     * rq;
                float x1 = qr[c*8 + e*2 + 1] * rq;
                unsigned short a0,a1,b0,b1;
                split_f16(x0, a0, b0);
                split_f16(x1, a1, b1);
                qh4[e] = (uint32_t)a0 | ((uint32_t)a1 << 16);
                ql4[e] = (uint32_t)b0 | ((uint32_t)b1 << 16);
                float y0 = kr[c*8 + e*2]     * rk;
                float y1 = kr[c*8 + e*2 + 1] * rk;
                split_f16(y0, a0, b0);
                split_f16(y1, a1, b1);
                kh4[e] = (uint32_t)a0 | ((uint32_t)a1 << 16);
                kl4[e] = (uint32_t)b0 | ((uint32_t)b1 << 16);
            }
            uint32_t so = sw64(r, c);
            *(uint4*)(smc + AT_QH + so) = make_uint4(qh4[0],qh4[1],qh4[2],qh4[3]);
            *(uint4*)(smc + AT_QL + so) = make_uint4(ql4[0],ql4[1],ql4[2],ql4[3]);
            *(uint4*)(smc + AT_KH + so) = make_uint4(kh4[0],kh4[1],kh4[2],kh4[3]);
            *(uint4*)(smc + AT_KL + so) = make_uint4(kl4[0],kl4[1],kl4[2],kl4[3]);
        }

        // V transposed hi/lo: Vt[d][j] = V[j][d]
        const float4* Vr = (const float4*)(Vg + (size_t)r * HD);
#pragma unroll
        for (int c = 0; c < 8; c++) {
            float4 v4 = Vr[c];
            float vv[4] = {v4.x, v4.y, v4.z, v4.w};
#pragma unroll
            for (int e = 0; e < 4; e++) {
                int d = c*4 + e;
                unsigned short hh, hl;
                split_f16(vv[e], hh, hl);
                *(unsigned short*)(smc + AT_VH + d*272 + r*2) = hh;
                *(unsigned short*)(smc + AT_VL + d*272 + r*2) = hl;
            }
        }
    }
    __syncthreads();

    // ---------------- QK^T ----------------
    int m0w = wid * 32;
    int aR = lane & 15;
    int aC = lane >> 4;
    int bR = (lane & 7) + ((lane >> 4) & 1) * 8;
    int bC = (lane >> 3) & 1;

    float s[2][16][4];
#pragma unroll
    for (int i = 0; i < 2; i++)
#pragma unroll
        for (int j = 0; j < 16; j++)
#pragma unroll
            for (int k = 0; k < 4; k++) s[i][j][k] = 0.0f;

    const uint32_t qoff[3] = {AT_QH, AT_QH, AT_QL};
    const uint32_t koff[3] = {AT_KH, AT_KL, AT_KH};
#pragma unroll
    for (int p = 0; p < 3; p++) {
#pragma unroll
        for (int kt = 0; kt < 2; kt++) {
            uint32_t a0[4], a1[4];
            ldsm_x4(a0, sb + qoff[p] + sw64(m0w + aR,      aC + 2*kt));
            ldsm_x4(a1, sb + qoff[p] + sw64(m0w + 16 + aR, aC + 2*kt));
#pragma unroll
            for (int nb = 0; nb < 8; nb++) {
                uint32_t b4[4];
                ldsm_x4(b4, sb + koff[p] + sw64(nb*16 + bR, bC + 2*kt));
                mma16816h(s[0][nb*2+0], a0, b4[0], b4[1]);
                mma16816h(s[0][nb*2+1], a0, b4[2], b4[3]);
                mma16816h(s[1][nb*2+0], a1, b4[0], b4[1]);
                mma16816h(s[1][nb*2+1], a1, b4[2], b4[3]);
            }
        }
    }
    __syncthreads();   // all Q/K smem reads complete before P overwrites

    // ------- softmax (static max, P scaled by 2^14 before fp16 cast) ------
    const float* rpb_h = g_rpb + (size_t)h * (NTOK * NTOK);
    float inv[2][2];
#pragma unroll
    for (int mt = 0; mt < 2; mt++) {
        int ri0 = m0w + mt*16 + (lane >> 2);
        int ri1 = ri0 + 8;
        bool v0 = ri0 < NTOK, v1 = ri1 < NTOK;
        const float* rp0 = rpb_h + (size_t)(v0 ? ri0 : 0) * NTOK;
        const float* rp1 = rpb_h + (size_t)(v1 ? ri1 : 0) * NTOK;
        float s0 = 0.f, s1 = 0.f;
#pragma unroll
        for (int nb = 0; nb < 16; nb++) {
            int j0 = nb*8 + (lane & 3)*2;
            float e0 = (v0 && j0   < NTOK) ? __expf(s[mt][nb][0] + rp0[j0]   - smax) * P_SCALE : 0.f;
            float e1 = (v0 && j0+1 < NTOK) ? __expf(s[mt][nb][1] + rp0[j0+1] - smax) * P_SCALE : 0.f;
            float e2 = (v1 && j0   < NTOK) ? __expf(s[mt][nb][2] + rp1[j0]   - smax) * P_SCALE : 0.f;
            float e3 = (v1 && j0+1 < NTOK) ? __expf(s[mt][nb][3] + rp1[j0+1] - smax) * P_SCALE : 0.f;
            s0 += e0 + e1;
            s1 += e2 + e3;
            *(uint32_t*)(smc + AT_P + ri0*272 + j0*2) = h2pack(e0, e1);
            *(uint32_t*)(smc + AT_P + ri1*272 + j0*2) = h2pack(e2, e3);
        }
        s0 += __shfl_xor_sync(0xFFFFFFFFu, s0, 1);
        s0 += __shfl_xor_sync(0xFFFFFFFFu, s0, 2);
        s1 += __shfl_xor_sync(0xFFFFFFFFu, s1, 1);
        s1 += __shfl_xor_sync(0xFFFFFFFFu, s1, 2);
        inv[mt][0] = (s0 > 0.f) ? 1.0f / s0 : 0.f;
        inv[mt][1] = (s1 > 0.f) ? 1.0f / s1 : 0.f;
    }
    __syncthreads();   // P visible to all

    // ---------------- PV: A from P (ldmatrix), B from Vt ----------------
    float o[2][4][4];
#pragma unroll
    for (int i = 0; i < 2; i++)
#pragma unroll
        for (int j = 0; j < 4; j++)
#pragma unroll
            for (int k = 0; k < 4; k++) o[i][j][k] = 0.0f;

    int vR = (lane & 7) + ((lane >> 4) & 1) * 8;
    int vC = (lane >> 3) & 1;
#pragma unroll
    for (int kt = 0; kt < 8; kt++) {
        uint32_t pa0[4], pa1[4];
        ldsm_x4(pa0, sb + AT_P + (uint32_t)(m0w + aR)      * 272 + (uint32_t)(aC + 2*kt) * 16);
        ldsm_x4(pa1, sb + AT_P + (uint32_t)(m0w + 16 + aR) * 272 + (uint32_t)(aC + 2*kt) * 16);
#pragma unroll
        for (int p = 0; p < 2; p++) {
            uint32_t voff = p ? AT_VL : AT_VH;
            uint32_t bv0[4], bv1[4];
            ldsm_x4(bv0, sb + voff + (uint32_t)(vR)      * 272 + (uint32_t)(vC + 2*kt) * 16);
            ldsm_x4(bv1, sb + voff + (uint32_t)(vR + 16) * 272 + (uint32_t)(vC + 2*kt) * 16);
            mma16816h(o[0][0], pa0, bv0[0], bv0[1]);
            mma16816h(o[0][1], pa0, bv0[2], bv0[3]);
            mma16816h(o[0][2], pa0, bv1[0], bv1[1]);
            mma16816h(o[0][3], pa0, bv1[2], bv1[3]);
            mma16816h(o[1][0], pa1, bv0[0], bv0[1]);
            mma16816h(o[1][1], pa1, bv0[2], bv0[3]);
            mma16816h(o[1][2], pa1, bv1[0], bv1[1]);
            mma16816h(o[1][3], pa1, bv1[2], bv1[3]);
        }
    }

    // ---------------- write output (fp16 hi/lo) ----------------
#pragma unroll
    for (int mt = 0; mt < 2; mt++) {
#pragma unroll
        for (int rh = 0; rh < 2; rh++) {
            int ri = m0w + mt*16 + (lane >> 2) + rh*8;
            if (ri >= NTOK) continue;
            float iv = inv[mt][rh];
            size_t row = ((size_t)b * NTOK + ri) * DIM + (size_t)h * HD;
#pragma unroll
            for (int nt = 0; nt < 4; nt++) {
                int d0 = nt*8 + (lane & 3)*2;
                float x0 = o[mt][nt][rh*2+0] * iv;
                float x1 = o[mt][nt][rh*2+1] * iv;
                unsigned short h0, h1, l0, l1;
                split_f16(x0, h0, l0);
                split_f16(x1, h1, l1);
                *(uint32_t*)(g_oh + row + d0) = (uint32_t)h0 | ((uint32_t)h1 << 16);
                *(uint32_t*)(g_ol + row + d0) = (uint32_t)l0 | ((uint32_t)l1 << 16);
            }
        }
    }
}

// ---------------------------------------------------------------------------
// kernel_launch — 5 launches; index 3 = attn_kernel (profiled)
// ---------------------------------------------------------------------------
extern "C" void kernel_launch(void* const* d_in, const int* in_sizes, int n_in,
                              void* d_out, int out_size)
{
    const float* x           = (const float*)d_in[0];
    const float* qkv_w       = (const float*)d_in[1];
    const float* q_bias      = (const float*)d_in[2];
    const float* v_bias      = (const float*)d_in[3];
    const float* logit_scale = (const float*)d_in[4];
    const float* cpb_w1      = (const float*)d_in[5];
    const float* cpb_b1      = (const float*)d_in[6];
    const float* cpb_w2      = (const float*)d_in[7];
    const float* proj_w      = (const float*)d_in[8];
    const float* proj_b      = (const float*)d_in[9];
    float* out = (float*)d_out;

    __half *xh, *xl, *oh, *ol, *wq, *wp;
    cudaGetSymbolAddress((void**)&xh, g_xh);
    cudaGetSymbolAddress((void**)&xl, g_xl);
    cudaGetSymbolAddress((void**)&oh, g_oh);
    cudaGetSymbolAddress((void**)&ol, g_ol);
    cudaGetSymbolAddress((void**)&wq, g_wq);
    cudaGetSymbolAddress((void**)&wp, g_wp);

    static bool attr_set = false;
    if (!attr_set) {
        cudaFuncSetAttribute(attn_kernel,
                             cudaFuncAttributeMaxDynamicSharedMemorySize, ATTN_SMEM);
        cudaFuncSetAttribute(gemm_mma<true>,
                             cudaFuncAttributeMaxDynamicSharedMemorySize, GEMM_SMEM);
        cudaFuncSetAttribute(gemm_mma<false>,
                             cudaFuncAttributeMaxDynamicSharedMemorySize, GEMM_SMEM);
        attr_set = true;
    }

    // 0: fused converters
    cvt_all_kernel<<<NBX + NBQ + NBP, 256>>>((const float4*)x,
                                             (const float4*)qkv_w,
                                             (const float4*)proj_w);

    // 1: fused cpb + rpb
    rpb_fused_kernel<<<RPB_BLKS, 256>>>(cpb_w1, cpb_b1, cpb_w2);

    // 2: QKV GEMM
    {
        dim3 grid(6, MTILES);
        gemm_mma<true><<<grid, 256, GEMM_SMEM>>>(xh, xl, wq,
                                                 nullptr, q_bias, v_bias, nullptr);
    }

    // 3: MMA attention  <-- profiled launch index
    attn_kernel<<<BW * NH, 128, ATTN_SMEM>>>(logit_scale);

    // 4: proj GEMM
    {
        dim3 grid(2, MTILES);
        gemm_mma<false><<<grid, 256, GEMM_SMEM>>>(oh, ol, wp,
                                                  out, nullptr, nullptr, proj_b);
    }
}

// round 17
// speedup vs baseline: 1.2936x; 1.1387x over previous
#include <cuda_runtime.h>
#include <cuda_fp16.h>
#include <math.h>
#include <stdint.h>

// ---------------------------------------------------------------------------
// Problem constants
// ---------------------------------------------------------------------------
#define BW      2048
#define NTOK    98
#define DIM     256
#define NH      8
#define HD      32
#define TBL     507
#define HID     512
#define M_ROWS  (BW * NTOK)    // 200704
#define MTILES  (M_ROWS / 128) // 1568

typedef unsigned long long ull;

// ---------------------------------------------------------------------------
// mma / ldmatrix / cp.async helpers
// ---------------------------------------------------------------------------
__device__ __forceinline__ uint32_t smem_u32(const void* p) {
    uint32_t a;
    asm("{ .reg .u64 t; cvta.to.shared.u64 t, %1; cvt.u32.u64 %0, t; }"
        : "=r"(a) : "l"(p));
    return a;
}

__device__ __forceinline__ void ldsm_x4(uint32_t* r, uint32_t addr) {
    asm volatile("ldmatrix.sync.aligned.m8n8.x4.shared.b16 {%0,%1,%2,%3}, [%4];"
                 : "=r"(r[0]), "=r"(r[1]), "=r"(r[2]), "=r"(r[3]) : "r"(addr));
}

__device__ __forceinline__ void mma16816h(float* c, const uint32_t* a,
                                          uint32_t b0, uint32_t b1) {
    asm volatile("mma.sync.aligned.m16n8k16.row.col.f32.f16.f16.f32 "
                 "{%0,%1,%2,%3}, {%4,%5,%6,%7}, {%8,%9}, {%0,%1,%2,%3};"
                 : "+f"(c[0]), "+f"(c[1]), "+f"(c[2]), "+f"(c[3])
                 : "r"(a[0]), "r"(a[1]), "r"(a[2]), "r"(a[3]),
                   "r"(b0), "r"(b1));
}

#define CP16(dst, src) \
    asm volatile("cp.async.cg.shared.global [%0], [%1], 16;" \
                 :: "r"(dst), "l"(src) : "memory")
#define CP_COMMIT() asm volatile("cp.async.commit_group;" ::: "memory")
#define CP_WAIT2()  asm volatile("cp.async.wait_group 2;" ::: "memory")
#define CP_WAIT1()  asm volatile("cp.async.wait_group 1;" ::: "memory")
#define CP_WAIT0()  asm volatile("cp.async.wait_group 0;" ::: "memory")

// ---------------------------------------------------------------------------
// Device scratch
// ---------------------------------------------------------------------------
__device__ float g_qkv[3ull * BW * NH * NTOK * HD];
__device__ __half g_xh[(size_t)M_ROWS * DIM];
__device__ __half g_xl[(size_t)M_ROWS * DIM];
__device__ __half g_oh[(size_t)M_ROWS * DIM];
__device__ __half g_ol[(size_t)M_ROWS * DIM];
__device__ __half g_wq[768 * DIM];
__device__ __half g_wp[DIM * DIM];
__device__ float g_rpb[NH * NTOK * NTOK];   // [h][i(query)][j(key)]

// ---------------------------------------------------------------------------
// fp16 hi/lo split helpers
// ---------------------------------------------------------------------------
__device__ __forceinline__ void split_f16(float x, unsigned short& h, unsigned short& l) {
    __half hb = __float2half_rn(x);
    float hf = __half2float(hb);
    __half lb = __float2half_rn(x - hf);
    h = __half_as_ushort(hb);
    l = __half_as_ushort(lb);
}
__device__ __forceinline__ uint32_t h2pack(float a, float b) {
    __half2 p = __floats2half2_rn(a, b);
    return *(uint32_t*)&p;
}

// ---------------------------------------------------------------------------
// Fused converter
// ---------------------------------------------------------------------------
#define N4X  ((M_ROWS * DIM) / 4)
#define N4Q  ((768 * DIM) / 4)
#define N4P  ((DIM * DIM) / 4)
#define NBX  ((N4X + 255) / 256)
#define NBQ  ((N4Q + 255) / 256)
#define NBP  ((N4P + 255) / 256)

__global__ __launch_bounds__(256)
void cvt_all_kernel(const float4* __restrict__ x,
                    const float4* __restrict__ wq_f,
                    const float4* __restrict__ wp_f)
{
    int bid = blockIdx.x;
    if (bid < NBX) {
        int i = bid * 256 + threadIdx.x;
        if (i >= N4X) return;
        float4 v = x[i];
        unsigned short h0,h1,h2,h3,l0,l1,l2,l3;
        split_f16(v.x, h0, l0);
        split_f16(v.y, h1, l1);
        split_f16(v.z, h2, l2);
        split_f16(v.w, h3, l3);
        uint2 H, L;
        H.x = (uint32_t)h0 | ((uint32_t)h1 << 16);
        H.y = (uint32_t)h2 | ((uint32_t)h3 << 16);
        L.x = (uint32_t)l0 | ((uint32_t)l1 << 16);
        L.y = (uint32_t)l2 | ((uint32_t)l3 << 16);
        ((uint2*)g_xh)[i] = H;
        ((uint2*)g_xl)[i] = L;
    } else if (bid < NBX + NBQ) {
        int i = (bid - NBX) * 256 + threadIdx.x;
        if (i >= N4Q) return;
        float4 v = wq_f[i];
        uint2 o;
        o.x = h2pack(v.x, v.y);
        o.y = h2pack(v.z, v.w);
        ((uint2*)g_wq)[i] = o;
    } else {
        int i = (bid - NBX - NBQ) * 256 + threadIdx.x;
        if (i >= N4P) return;
        float4 v = wp_f[i];
        uint2 o;
        o.x = h2pack(v.x, v.y);
        o.y = h2pack(v.z, v.w);
        ((uint2*)g_wp)[i] = o;
    }
}

// ---------------------------------------------------------------------------
// Fused CPB MLP + rpb gather ([h][i][j])
// ---------------------------------------------------------------------------
__device__ __forceinline__ float rel_coord(float x, float w) {
    float t = x / (w - 1.0f + 1e-6f) * 8.0f;
    float l = log2f(fabsf(t) + 1.0f) * (1.0f / 3.0f);
    return (t > 0.0f) ? l : ((t < 0.0f) ? -l : 0.0f);
}

#define RPB_TOTAL (NH * NTOK * NTOK)
#define RPB_PER_BLK 1024
#define RPB_BLKS ((RPB_TOTAL + RPB_PER_BLK - 1) / RPB_PER_BLK)

__global__ __launch_bounds__(256)
void rpb_fused_kernel(const float* __restrict__ w1,
                      const float* __restrict__ b1,
                      const float* __restrict__ w2)
{
    __shared__ float s_w1[HID * 3];
    __shared__ float s_b1[HID];
    __shared__ float s_w2[NH * HID];
    __shared__ float s_bt[TBL * NH];

    int tid = threadIdx.x;
    for (int i = tid; i < HID * 3; i += 256) s_w1[i] = w1[i];
    for (int i = tid; i < HID; i += 256)     s_b1[i] = b1[i];
    for (int i = tid; i < NH * HID; i += 256) s_w2[i] = w2[i];
    __syncthreads();

    for (int t = tid; t < TBL; t += 256) {
        int a = t / 169;
        int b = (t / 13) % 13;
        int c = t % 13;
        float c0 = rel_coord((float)(a - 1), 2.0f);
        float c1 = rel_coord((float)(b - 6), 7.0f);
        float c2 = rel_coord((float)(c - 6), 7.0f);
        float acc[NH];
#pragma unroll
        for (int h = 0; h < NH; h++) acc[h] = 0.0f;
        for (int j = 0; j < HID; j++) {
            float hv = s_w1[j*3+0]*c0 + s_w1[j*3+1]*c1 + s_w1[j*3+2]*c2 + s_b1[j];
            hv = fmaxf(hv, 0.0f);
#pragma unroll
            for (int h = 0; h < NH; h++) acc[h] += hv * s_w2[h*HID + j];
        }
#pragma unroll
        for (int h = 0; h < NH; h++) s_bt[t*NH + h] = acc[h];
    }
    __syncthreads();

    int base = blockIdx.x * RPB_PER_BLK;
#pragma unroll
    for (int k = 0; k < RPB_PER_BLK / 256; k++) {
        int idx = base + k * 256 + tid;
        if (idx >= RPB_TOTAL) return;
        int h = idx / (NTOK * NTOK);
        int r = idx % (NTOK * NTOK);
        int i = r / NTOK, j = r % NTOK;
        int di = i / 49, hi = (i / 7) % 7, wi = i % 7;
        int dj = j / 49, hj = (j / 7) % 7, wj = j % 7;
        int t = (di - dj + 1) * 169 + (hi - hj + 6) * 13 + (wi - wj + 6);
        float v = s_bt[t*NH + h];
        g_rpb[idx] = 16.0f / (1.0f + __expf(-v));
    }
}

// ---------------------------------------------------------------------------
// fp16 2-pass GEMM — identical to R12-R16.
// ---------------------------------------------------------------------------
#define MATB  8192
#define STGB  (3 * MATB)
#define NSTG  3
#define GEMM_SMEM (NSTG * STGB)

__device__ __forceinline__ uint32_t sw64(int r, int c) {
    return (uint32_t)r * 64u + (uint32_t)((c ^ (r & 3)) << 4);
}

template<bool IS_QKV>
__global__ __launch_bounds__(256, 2)
void gemm_mma(const __half* __restrict__ Ah,
              const __half* __restrict__ Al,
              const __half* __restrict__ Bf,
              float* __restrict__ outp,
              const float* __restrict__ qb,
              const float* __restrict__ vb,
              const float* __restrict__ pb)
{
    extern __shared__ __align__(16) unsigned char smc[];
    const uint32_t sb = smem_u32(smc);

    int tid  = threadIdx.x;
    int lane = tid & 31;
    int wid  = tid >> 5;
    int wm   = wid & 3;
    int wn   = wid >> 2;
    int n0   = blockIdx.x * 128;
    int m0   = blockIdx.y * 128;

    const char* srcs[3] = {
        (const char*)Ah + (size_t)m0 * 512,
        (const char*)Al + (size_t)m0 * 512,
        (const char*)Bf + (size_t)n0 * 512
    };

    auto issue = [&](int ck, int buf) {
        uint32_t st = sb + (uint32_t)buf * STGB;
#pragma unroll
        for (int t = 0; t < 6; t++) {
            int m = t >> 1;
            int s = tid + (t & 1) * 256;
            int r = s >> 2, c = s & 3;
            uint32_t dst = st + (uint32_t)m * MATB + sw64(r, c);
            const char* src = srcs[m] + (size_t)r * 512 + ck * 64 + c * 16;
            CP16(dst, src);
        }
    };

    issue(0, 0); CP_COMMIT();
    issue(1, 1); CP_COMMIT();
    issue(2, 2); CP_COMMIT();

    int aRow = wm * 32 + (lane & 15);
    int aC   = lane >> 4;
    int bRow = wn * 64 + (lane & 7) + ((lane >> 4) & 1) * 8;
    int bC   = (lane >> 3) & 1;

    float acc[2][8][4];
#pragma unroll
    for (int i = 0; i < 2; i++)
#pragma unroll
        for (int j = 0; j < 8; j++)
#pragma unroll
            for (int k = 0; k < 4; k++) acc[i][j][k] = 0.0f;

    for (int c = 0; c < 8; c++) {
        if (c <= 5)      CP_WAIT2();
        else if (c == 6) CP_WAIT1();
        else             CP_WAIT0();
        __syncthreads();

        uint32_t st = sb + (uint32_t)(c % 3) * STGB;
        uint32_t stAH = st, stAL = st + MATB, stBF = st + 2*MATB;

#pragma unroll
        for (int kk = 0; kk < 2; kk++) {
            uint32_t ah[2][4], al[2][4];
#pragma unroll
            for (int mt = 0; mt < 2; mt++) {
                int r = aRow + mt * 16;
                uint32_t off = sw64(r, aC + 2 * kk);
                ldsm_x4(ah[mt], stAH + off);
                ldsm_x4(al[mt], stAL + off);
            }
#pragma unroll
            for (int pr = 0; pr < 4; pr++) {
                int r = bRow + pr * 16;
                uint32_t off = sw64(r, bC + 2 * kk);
                uint32_t bf4[4];
                ldsm_x4(bf4, stBF + off);
#pragma unroll
                for (int mt = 0; mt < 2; mt++)
#pragma unroll
                    for (int hf = 0; hf < 2; hf++) {
                        int w2 = hf * 2;
                        float* a4 = acc[mt][pr * 2 + hf];
                        mma16816h(a4, ah[mt], bf4[w2], bf4[w2+1]);
                        mma16816h(a4, al[mt], bf4[w2], bf4[w2+1]);
                    }
            }
        }
        __syncthreads();
        if (c + 3 < 8) { issue(c + 3, c % 3); CP_COMMIT(); }
    }

    const size_t tstride = (size_t)BW * NH * NTOK * HD;
#pragma unroll
    for (int mt = 0; mt < 2; mt++) {
        int rA = m0 + wm*32 + mt*16 + (lane >> 2);
#pragma unroll
        for (int nt8 = 0; nt8 < 8; nt8++) {
            int n = n0 + wn*64 + nt8*8 + (lane & 3) * 2;
            if (IS_QKV) {
                int which = n >> 8;
                int h = (n >> 5) & 7;
                int d = n & 31;
                float2 bv = make_float2(0.f, 0.f);
                if (which == 0)      bv = *(const float2*)(qb + (n & 255));
                else if (which == 2) bv = *(const float2*)(vb + (n & 255));
                {
                    int bwin = rA / NTOK, tok = rA - bwin * NTOK;
                    float* dst = g_qkv + (size_t)which * tstride
                               + (((size_t)bwin * NH + h) * NTOK + tok) * HD + d;
                    *(float2*)dst = make_float2(acc[mt][nt8][0] + bv.x,
                                                acc[mt][nt8][1] + bv.y);
                }
                {
                    int r2 = rA + 8;
                    int bwin = r2 / NTOK, tok = r2 - bwin * NTOK;
                    float* dst = g_qkv + (size_t)which * tstride
                               + (((size_t)bwin * NH + h) * NTOK + tok) * HD + d;
                    *(float2*)dst = make_float2(acc[mt][nt8][2] + bv.x,
                                                acc[mt][nt8][3] + bv.y);
                }
            } else {
                float2 bv = *(const float2*)(pb + n);
                *(float2*)(outp + (size_t)rA * DIM + n) =
                    make_float2(acc[mt][nt8][0] + bv.x, acc[mt][nt8][1] + bv.y);
                *(float2*)(outp + (size_t)(rA + 8) * DIM + n) =
                    make_float2(acc[mt][nt8][2] + bv.x, acc[mt][nt8][3] + bv.y);
            }
        }
    }
}

// ---------------------------------------------------------------------------
// MMA attention — register P (C->A frag identity) + key-half splitting.
// smem: Vt hi/lo [32 x 136 f16] + Qh/Ql/Kh/Kl [128 x 32 f16, sw64] = 50176 B.
// P never touches smem; P scaled by 2^14 before fp16 to avoid subnormals.
// ---------------------------------------------------------------------------
#define AT_VH 0
#define AT_VL 8704
#define AT_QH 17408
#define AT_QL 25600
#define AT_KH 33792
#define AT_KL 41984
#define ATTN_SMEM 50176
#define P_SCALE 16384.0f

__global__ __launch_bounds__(128, 3)
void attn_kernel(const float* __restrict__ logit_scale)
{
    extern __shared__ __align__(16) unsigned char smc[];
    const uint32_t sb = smem_u32(smc);
    int bh = blockIdx.x;
    int b = bh >> 3, h = bh & 7;
    int tid = threadIdx.x;
    int lane = tid & 31, wid = tid >> 5;

    // zero only Vt region (masked-P x garbage-V must not produce NaN)
    for (int i = tid; i < 17408 / 16; i += 128)
        ((uint4*)smc)[i] = make_uint4(0u, 0u, 0u, 0u);
    __syncthreads();

    float scale = __expf(fminf(logit_scale[h], 4.6051702f));
    float smax = scale + 16.0f;

    const size_t tstride = (size_t)BW * NH * NTOK * HD;
    size_t base = ((size_t)b * NH + h) * (NTOK * HD);
    const float* Qg = g_qkv + base;
    const float* Kg = g_qkv + tstride + base;
    const float* Vg = g_qkv + 2 * tstride + base;

    int r = tid;
    if (r < NTOK) {
        float qr[32], kr[32];
        float nq = 0.f, nk = 0.f;
        const float4* Qr = (const float4*)(Qg + (size_t)r * HD);
        const float4* Kr = (const float4*)(Kg + (size_t)r * HD);
#pragma unroll
        for (int c = 0; c < 8; c++) {
            float4 t = Qr[c];
            qr[c*4+0]=t.x; qr[c*4+1]=t.y; qr[c*4+2]=t.z; qr[c*4+3]=t.w;
            nq += t.x*t.x + t.y*t.y + t.z*t.z + t.w*t.w;
            float4 u = Kr[c];
            kr[c*4+0]=u.x; kr[c*4+1]=u.y; kr[c*4+2]=u.z; kr[c*4+3]=u.w;
            nk += u.x*u.x + u.y*u.y + u.z*u.z + u.w*u.w;
        }
        float rq = scale / fmaxf(sqrtf(nq), 1e-12f);
        float rk = 1.0f / fmaxf(sqrtf(nk), 1e-12f);

#pragma unroll
        for (int c = 0; c < 4; c++) {
            uint32_t qh4[4], ql4[4], kh4[4], kl4[4];
#pragma unroll
            for (int e = 0; e < 4; e++) {
                float x0 = qr[c*8 + e*2]     * rq;
                float x1 = qr[c*8 + e*2 + 1] * rq;
                unsigned short a0,a1,b0,b1;
                split_f16(x0, a0, b0);
                split_f16(x1, a1, b1);
                qh4[e] = (uint32_t)a0 | ((uint32_t)a1 << 16);
                ql4[e] = (uint32_t)b0 | ((uint32_t)b1 << 16);
                float y0 = kr[c*8 + e*2]     * rk;
                float y1 = kr[c*8 + e*2 + 1] * rk;
                split_f16(y0, a0, b0);
                split_f16(y1, a1, b1);
                kh4[e] = (uint32_t)a0 | ((uint32_t)a1 << 16);
                kl4[e] = (uint32_t)b0 | ((uint32_t)b1 << 16);
            }
            uint32_t so = sw64(r, c);
            *(uint4*)(smc + AT_QH + so) = make_uint4(qh4[0],qh4[1],qh4[2],qh4[3]);
            *(uint4*)(smc + AT_QL + so) = make_uint4(ql4[0],ql4[1],ql4[2],ql4[3]);
            *(uint4*)(smc + AT_KH + so) = make_uint4(kh4[0],kh4[1],kh4[2],kh4[3]);
            *(uint4*)(smc + AT_KL + so) = make_uint4(kl4[0],kl4[1],kl4[2],kl4[3]);
        }

        // V transposed hi/lo: Vt[d][j] = V[j][d]
        const float4* Vr = (const float4*)(Vg + (size_t)r * HD);
#pragma unroll
        for (int c = 0; c < 8; c++) {
            float4 v4 = Vr[c];
            float vv[4] = {v4.x, v4.y, v4.z, v4.w};
#pragma unroll
            for (int e = 0; e < 4; e++) {
                int d = c*4 + e;
                unsigned short hh, hl;
                split_f16(vv[e], hh, hl);
                *(unsigned short*)(smc + AT_VH + d*272 + r*2) = hh;
                *(unsigned short*)(smc + AT_VL + d*272 + r*2) = hl;
            }
        }
    }
    __syncthreads();

    int m0w = wid * 32;
    int aR = lane & 15;
    int aC = lane >> 4;
    int bR = (lane & 7) + ((lane >> 4) & 1) * 8;
    int bC = (lane >> 3) & 1;
    int vR = bR;
    int vC = bC;

    const float* rpb_h = g_rpb + (size_t)h * (NTOK * NTOK);
    int ri0q = m0w + (lane >> 2);

    float o[2][4][4];
#pragma unroll
    for (int i = 0; i < 2; i++)
#pragma unroll
        for (int j = 0; j < 4; j++)
#pragma unroll
            for (int k = 0; k < 4; k++) o[i][j][k] = 0.0f;
    float rs[2][2] = {{0.f, 0.f}, {0.f, 0.f}};

    const uint32_t qoff[3] = {AT_QH, AT_QH, AT_QL};
    const uint32_t koff[3] = {AT_KH, AT_KL, AT_KH};

#pragma unroll
    for (int hf = 0; hf < 2; hf++) {
        // ---- QK^T for keys [hf*64, hf*64+64) ----
        float s[2][8][4];
#pragma unroll
        for (int i = 0; i < 2; i++)
#pragma unroll
            for (int j = 0; j < 8; j++)
#pragma unroll
                for (int k = 0; k < 4; k++) s[i][j][k] = 0.0f;

#pragma unroll
        for (int p = 0; p < 3; p++) {
#pragma unroll
            for (int kt = 0; kt < 2; kt++) {
                uint32_t a0[4], a1[4];
                ldsm_x4(a0, sb + qoff[p] + sw64(m0w + aR,      aC + 2*kt));
                ldsm_x4(a1, sb + qoff[p] + sw64(m0w + 16 + aR, aC + 2*kt));
#pragma unroll
                for (int nb = 0; nb < 4; nb++) {
                    uint32_t b4[4];
                    ldsm_x4(b4, sb + koff[p] + sw64(hf*64 + nb*16 + bR, bC + 2*kt));
                    mma16816h(s[0][nb*2+0], a0, b4[0], b4[1]);
                    mma16816h(s[0][nb*2+1], a0, b4[2], b4[3]);
                    mma16816h(s[1][nb*2+0], a1, b4[0], b4[1]);
                    mma16816h(s[1][nb*2+1], a1, b4[2], b4[3]);
                }
            }
        }

        // ---- softmax-exp (static max, masked, scaled) ----
#pragma unroll
        for (int mt = 0; mt < 2; mt++) {
            int ri0 = ri0q + mt*16;
            int ri1 = ri0 + 8;
            bool v0 = ri0 < NTOK, v1 = ri1 < NTOK;
            const float* rp0 = rpb_h + (size_t)(v0 ? ri0 : 0) * NTOK;
            const float* rp1 = rpb_h + (size_t)(v1 ? ri1 : 0) * NTOK;
#pragma unroll
            for (int nb = 0; nb < 8; nb++) {
                int j0 = hf*64 + nb*8 + (lane & 3)*2;
                float e0 = (v0 && j0   < NTOK) ? __expf(s[mt][nb][0] + rp0[j0]   - smax) * P_SCALE : 0.f;
                float e1 = (v0 && j0+1 < NTOK) ? __expf(s[mt][nb][1] + rp0[j0+1] - smax) * P_SCALE : 0.f;
                float e2 = (v1 && j0   < NTOK) ? __expf(s[mt][nb][2] + rp1[j0]   - smax) * P_SCALE : 0.f;
                float e3 = (v1 && j0+1 < NTOK) ? __expf(s[mt][nb][3] + rp1[j0+1] - smax) * P_SCALE : 0.f;
                rs[mt][0] += e0 + e1;
                rs[mt][1] += e2 + e3;
                s[mt][nb][0] = e0; s[mt][nb][1] = e1;
                s[mt][nb][2] = e2; s[mt][nb][3] = e3;
            }
        }

        // ---- PV for this key half: register C->A frag conversion ----
#pragma unroll
        for (int ktl = 0; ktl < 4; ktl++) {
            int kt = hf*4 + ktl;
            uint32_t ph0[4], ph1[4];
            ph0[0] = h2pack(s[0][2*ktl][0],   s[0][2*ktl][1]);
            ph0[1] = h2pack(s[0][2*ktl][2],   s[0][2*ktl][3]);
            ph0[2] = h2pack(s[0][2*ktl+1][0], s[0][2*ktl+1][1]);
            ph0[3] = h2pack(s[0][2*ktl+1][2], s[0][2*ktl+1][3]);
            ph1[0] = h2pack(s[1][2*ktl][0],   s[1][2*ktl][1]);
            ph1[1] = h2pack(s[1][2*ktl][2],   s[1][2*ktl][3]);
            ph1[2] = h2pack(s[1][2*ktl+1][0], s[1][2*ktl+1][1]);
            ph1[3] = h2pack(s[1][2*ktl+1][2], s[1][2*ktl+1][3]);
#pragma unroll
            for (int p = 0; p < 2; p++) {
                uint32_t voff = p ? AT_VL : AT_VH;
                uint32_t bv0[4], bv1[4];
                ldsm_x4(bv0, sb + voff + (uint32_t)(vR)      * 272 + (uint32_t)(vC + 2*kt) * 16);
                ldsm_x4(bv1, sb + voff + (uint32_t)(vR + 16) * 272 + (uint32_t)(vC + 2*kt) * 16);
                mma16816h(o[0][0], ph0, bv0[0], bv0[1]);
                mma16816h(o[0][1], ph0, bv0[2], bv0[3]);
                mma16816h(o[0][2], ph0, bv1[0], bv1[1]);
                mma16816h(o[0][3], ph0, bv1[2], bv1[3]);
                mma16816h(o[1][0], ph1, bv0[0], bv0[1]);
                mma16816h(o[1][1], ph1, bv0[2], bv0[3]);
                mma16816h(o[1][2], ph1, bv1[0], bv1[1]);
                mma16816h(o[1][3], ph1, bv1[2], bv1[3]);
            }
        }
    }

    // ---- finalize row sums (quad reduce) and write output ----
    float inv[2][2];
#pragma unroll
    for (int mt = 0; mt < 2; mt++) {
        float s0 = rs[mt][0], s1 = rs[mt][1];
        s0 += __shfl_xor_sync(0xFFFFFFFFu, s0, 1);
        s0 += __shfl_xor_sync(0xFFFFFFFFu, s0, 2);
        s1 += __shfl_xor_sync(0xFFFFFFFFu, s1, 1);
        s1 += __shfl_xor_sync(0xFFFFFFFFu, s1, 2);
        inv[mt][0] = (s0 > 0.f) ? 1.0f / s0 : 0.f;
        inv[mt][1] = (s1 > 0.f) ? 1.0f / s1 : 0.f;
    }

#pragma unroll
    for (int mt = 0; mt < 2; mt++) {
#pragma unroll
        for (int rh = 0; rh < 2; rh++) {
            int ri = ri0q + mt*16 + rh*8;
            if (ri >= NTOK) continue;
            float iv = inv[mt][rh];
            size_t row = ((size_t)b * NTOK + ri) * DIM + (size_t)h * HD;
#pragma unroll
            for (int nt = 0; nt < 4; nt++) {
                int d0 = nt*8 + (lane & 3)*2;
                float x0 = o[mt][nt][rh*2+0] * iv;
                float x1 = o[mt][nt][rh*2+1] * iv;
                unsigned short h0, h1, l0, l1;
                split_f16(x0, h0, l0);
                split_f16(x1, h1, l1);
                *(uint32_t*)(g_oh + row + d0) = (uint32_t)h0 | ((uint32_t)h1 << 16);
                *(uint32_t*)(g_ol + row + d0) = (uint32_t)l0 | ((uint32_t)l1 << 16);
            }
        }
    }
}

// ---------------------------------------------------------------------------
// kernel_launch — 5 launches; index 3 = attn_kernel (profiled)
// ---------------------------------------------------------------------------
extern "C" void kernel_launch(void* const* d_in, const int* in_sizes, int n_in,
                              void* d_out, int out_size)
{
    const float* x           = (const float*)d_in[0];
    const float* qkv_w       = (const float*)d_in[1];
    const float* q_bias      = (const float*)d_in[2];
    const float* v_bias      = (const float*)d_in[3];
    const float* logit_scale = (const float*)d_in[4];
    const float* cpb_w1      = (const float*)d_in[5];
    const float* cpb_b1      = (const float*)d_in[6];
    const float* cpb_w2      = (const float*)d_in[7];
    const float* proj_w      = (const float*)d_in[8];
    const float* proj_b      = (const float*)d_in[9];
    float* out = (float*)d_out;

    __half *xh, *xl, *oh, *ol, *wq, *wp;
    cudaGetSymbolAddress((void**)&xh, g_xh);
    cudaGetSymbolAddress((void**)&xl, g_xl);
    cudaGetSymbolAddress((void**)&oh, g_oh);
    cudaGetSymbolAddress((void**)&ol, g_ol);
    cudaGetSymbolAddress((void**)&wq, g_wq);
    cudaGetSymbolAddress((void**)&wp, g_wp);

    static bool attr_set = false;
    if (!attr_set) {
        cudaFuncSetAttribute(attn_kernel,
                             cudaFuncAttributeMaxDynamicSharedMemorySize, ATTN_SMEM);
        cudaFuncSetAttribute(gemm_mma<true>,
                             cudaFuncAttributeMaxDynamicSharedMemorySize, GEMM_SMEM);
        cudaFuncSetAttribute(gemm_mma<false>,
                             cudaFuncAttributeMaxDynamicSharedMemorySize, GEMM_SMEM);
        attr_set = true;
    }

    // 0: fused converters
    cvt_all_kernel<<<NBX + NBQ + NBP, 256>>>((const float4*)x,
                                             (const float4*)qkv_w,
                                             (const float4*)proj_w);

    // 1: fused cpb + rpb
    rpb_fused_kernel<<<RPB_BLKS, 256>>>(cpb_w1, cpb_b1, cpb_w2);

    // 2: QKV GEMM
    {
        dim3 grid(6, MTILES);
        gemm_mma<true><<<grid, 256, GEMM_SMEM>>>(xh, xl, wq,
                                                 nullptr, q_bias, v_bias, nullptr);
    }

    // 3: MMA attention  <-- profiled launch index
    attn_kernel<<<BW * NH, 128, ATTN_SMEM>>>(logit_scale);

    // 4: proj GEMM
    {
        dim3 grid(2, MTILES);
        gemm_mma<false><<<grid, 256, GEMM_SMEM>>>(oh, ol, wp,
                                                  out, nullptr, nullptr, proj_b);
    }
}